// round 11
// baseline (speedup 1.0000x reference)
#include <cuda_runtime.h>
#include <cstdint>

#define NF     12
#define NPAIR  66
#define NCOMB  781
#define NCOLS  793
#define NROWS  32768
#define WPB    8            // warps per block
#define RPW    2            // rows per warp (per unit)
#define UNITS  2            // sequential row-pair units per warp
#define NVAL   148          // slots: 0..11 s, 12..77 pairs, 78 one, 80..145 -pairs

typedef unsigned long long ull;

// pair id, lexicographic i<j
constexpr int pid(int i, int j) { return i * (2 * NF - i - 1) / 2 + (j - i - 1); }

// ---------------------------------------------------------------------------
// Combo table: two 16-bit BYTE offsets into val[NVAL][2] (8 B per slot).
// A-offset points into the negated-pair region so q = fma(A, B, 1) = 1 - |a|b.
// ---------------------------------------------------------------------------
struct CTbl { uint32_t v[NCOMB]; };
struct PTbl { uint32_t v[NPAIR]; };

constexpr CTbl make_ctbl() {
    CTbl t{};
    int p = 0;
    for (int i = 0; i < NF; ++i)                    // size 2: (-P2) * 1
        for (int j = i + 1; j < NF; ++j)
            t.v[p++] = (uint32_t)((80 + pid(i, j)) * 8)
                     | ((uint32_t)(78 * 8) << 16);
    for (int i = 0; i < NF; ++i)                    // size 3: (-P2(i,j)) * s_k
        for (int j = i + 1; j < NF; ++j)
            for (int k = j + 1; k < NF; ++k)
                t.v[p++] = (uint32_t)((80 + pid(i, j)) * 8)
                         | ((uint32_t)(k * 8) << 16);
    for (int i = 0; i < NF; ++i)                    // size 4: (-P2(i,j))*P2(k,l)
        for (int j = i + 1; j < NF; ++j)
            for (int k = j + 1; k < NF; ++k)
                for (int l = k + 1; l < NF; ++l)
                    t.v[p++] = (uint32_t)((80 + pid(i, j)) * 8)
                             | ((uint32_t)((12 + pid(k, l)) * 8) << 16);
    return t;
}
constexpr PTbl make_ptbl() {
    PTbl t{};
    int p = 0;
    for (int i = 0; i < NF; ++i)
        for (int j = i + 1; j < NF; ++j)
            t.v[p++] = (uint32_t)i | ((uint32_t)j << 8);
    return t;
}

__device__ const CTbl d_ct = make_ctbl();
__device__ const PTbl d_pt = make_ptbl();

// ---- packed f32x2 helpers ----------------------------------------------------
__device__ __forceinline__ ull fma2(ull a, ull b, ull c) {
    ull d; asm("fma.rn.f32x2 %0,%1,%2,%3;" : "=l"(d) : "l"(a), "l"(b), "l"(c));
    return d;
}
__device__ __forceinline__ ull mul2(ull a, ull b) {
    ull d; asm("mul.rn.f32x2 %0,%1,%2;" : "=l"(d) : "l"(a), "l"(b));
    return d;
}
__device__ __forceinline__ ull pack2(float x, float y) {
    ull r;
    asm("mov.b64 %0,{%1,%2};" : "=l"(r)
        : "r"(__float_as_uint(x)), "r"(__float_as_uint(y)));
    return r;
}
__device__ __forceinline__ void unpack2(ull v, float& x, float& y) {
    uint32_t a, b;
    asm("mov.b64 {%0,%1},%2;" : "=r"(a), "=r"(b) : "l"(v));
    x = __uint_as_float(a); y = __uint_as_float(b);
}
__device__ __forceinline__ float lg2a(float x) {
    float r; asm("lg2.approx.f32 %0,%1;" : "=f"(r) : "f"(x)); return r;
}
__device__ __forceinline__ float ex2a(float x) {
    float r; asm("ex2.approx.f32 %0,%1;" : "=f"(r) : "f"(x)); return r;
}

// ---------------------------------------------------------------------------
// 1024 blocks -> single fully-resident wave (<=1184 slots). Each warp runs
// UNITS=2 sequential row-pairs through the proven R9 inner loop.
// ---------------------------------------------------------------------------
__global__ __launch_bounds__(256)
void schweizer_kernel(const float* __restrict__ x,
                      const float* __restrict__ lam_p,
                      float* __restrict__ out)
{
    __shared__ __align__(8) float val[WPB][NVAL][RPW];

    const int lane = threadIdx.x & 31;
    const int wrp  = threadIdx.x >> 5;

    const float lam = __ldg(lam_p);
    const float inv = 1.0f / lam;

    const ull ONES = pack2(1.0f, 1.0f);
    const ull MN1  = pack2(-1.0f, -1.0f);
    const ull INV2 = pack2(inv, inv);

    float (*v)[RPW] = val[wrp];
    const char* vb = (const char*)v;

    #pragma unroll
    for (int u = 0; u < UNITS; ++u) {
        const int r0 = (blockIdx.x * UNITS + u) * (WPB * RPW) + wrp * RPW;

        // ---- prologue: s_i for 2 rows + passthrough -------------------------
        if (lane < RPW * NF) {
            const float xv = x[(size_t)r0 * NF + lane];
            const int f = lane % NF, r = lane / NF;
            v[f][r] = 1.0f - __powf(1.0f - xv, lam);
            out[(size_t)(r0 + r) * NCOLS + f] = xv;
        } else if (lane < RPW * NF + RPW) {
            v[78][lane - RPW * NF] = 1.0f;                   // sentinel
        }
        __syncwarp();

        // ---- 66 pairwise products + negated copies --------------------------
        #pragma unroll
        for (int p = lane; p < NPAIR; p += 32) {
            const uint32_t w = d_pt.v[p];
            const float2 a = *(const float2*)v[w & 0xFFu];
            const float2 b = *(const float2*)v[w >> 8];
            float2 r2, n2;
            r2.x = a.x * b.x;  r2.y = a.y * b.y;
            n2.x = -r2.x;      n2.y = -r2.y;
            *(float2*)v[12 + p] = r2;
            *(float2*)v[80 + p] = n2;
        }
        __syncwarp();

        // ---- main sweep: 24 full 32-column groups + 13-column tail ----------
        float* __restrict__ o0 = out + (size_t)r0 * NCOLS + NF;
        float* __restrict__ o1 = o0 + NCOLS;

        #pragma unroll 4
        for (int k = 0; k < 24; ++k) {
            const int c = k * 32 + lane;
            const uint32_t w = d_ct.v[c];
            const ull A = *(const ull*)(vb + (w & 0xFFFFu));  // (-a0, -a1)
            const ull B = *(const ull*)(vb + (w >> 16));      // ( b0,  b1)
            const ull Q = fma2(A, B, ONES);                   // 1 - a*b
            float q0, q1; unpack2(Q, q0, q1);
            const ull M = mul2(pack2(lg2a(q0), lg2a(q1)), INV2);
            float m0, m1; unpack2(M, m0, m1);
            const ull R = fma2(pack2(ex2a(m0), ex2a(m1)), MN1, ONES);
            float r0v, r1v; unpack2(R, r0v, r1v);
            o0[c] = r0v;
            o1[c] = r1v;
        }
        if (lane < NCOMB - 768) {                             // cols 768..780
            const int c = 768 + lane;
            const uint32_t w = d_ct.v[c];
            const float* pa = (const float*)(vb + (w & 0xFFFFu));
            const float* pb = (const float*)(vb + (w >> 16));
            const float q0 = fmaf(pa[0], pb[0], 1.0f);
            const float q1 = fmaf(pa[1], pb[1], 1.0f);
            o0[c] = 1.0f - ex2a(lg2a(q0) * inv);
            o1[c] = 1.0f - ex2a(lg2a(q1) * inv);
        }
        __syncwarp();
    }
}

extern "C" void kernel_launch(void* const* d_in, const int* in_sizes, int n_in,
                              void* d_out, int out_size)
{
    const float* x   = (const float*)d_in[0];
    const float* lam = (const float*)d_in[1];
    float*       out = (float*)d_out;

    schweizer_kernel<<<NROWS / (WPB * RPW * UNITS), 256>>>(x, lam, out);
}

// round 12
// speedup vs baseline: 1.0770x; 1.0770x over previous
#include <cuda_runtime.h>
#include <cstdint>

#define NF     12
#define NPAIR  66
#define NCOMB  781
#define NCOLS  793
#define NROWS  32768
#define WPB    8            // warps per block
#define RPW    2            // rows per warp
#define NVAL   80           // slots: 0..11 s_i, 12..77 pairs, 78 = 1.0, pad

// pair id, lexicographic i<j
constexpr int pid(int i, int j) { return i * (2 * NF - i - 1) / 2 + (j - i - 1); }

// ---------------------------------------------------------------------------
// Combo table: two 16-bit BYTE offsets into val[NVAL][2] (8 B per slot).
// combo value p = val[a] * val[b]; q = 1 - p via FFMA with negate modifier.
// ---------------------------------------------------------------------------
struct CTbl { uint32_t v[NCOMB]; };
struct PTbl { uint32_t v[NPAIR]; };

constexpr CTbl make_ctbl() {
    CTbl t{};
    int p = 0;
    for (int i = 0; i < NF; ++i)                    // size 2: P2 * 1
        for (int j = i + 1; j < NF; ++j)
            t.v[p++] = (uint32_t)((12 + pid(i, j)) * 8)
                     | ((uint32_t)(78 * 8) << 16);
    for (int i = 0; i < NF; ++i)                    // size 3: P2(i,j) * s_k
        for (int j = i + 1; j < NF; ++j)
            for (int k = j + 1; k < NF; ++k)
                t.v[p++] = (uint32_t)((12 + pid(i, j)) * 8)
                         | ((uint32_t)(k * 8) << 16);
    for (int i = 0; i < NF; ++i)                    // size 4: P2(i,j) * P2(k,l)
        for (int j = i + 1; j < NF; ++j)
            for (int k = j + 1; k < NF; ++k)
                for (int l = k + 1; l < NF; ++l)
                    t.v[p++] = (uint32_t)((12 + pid(i, j)) * 8)
                             | ((uint32_t)((12 + pid(k, l)) * 8) << 16);
    return t;
}
constexpr PTbl make_ptbl() {
    PTbl t{};
    int p = 0;
    for (int i = 0; i < NF; ++i)
        for (int j = i + 1; j < NF; ++j)
            t.v[p++] = (uint32_t)i | ((uint32_t)j << 8);
    return t;
}

__device__ const CTbl d_ct = make_ctbl();
__device__ const PTbl d_pt = make_ptbl();

__device__ __forceinline__ float lg2a(float x) {
    float r; asm("lg2.approx.f32 %0,%1;" : "=f"(r) : "f"(x)); return r;
}
__device__ __forceinline__ float ex2a(float x) {
    float r; asm("ex2.approx.f32 %0,%1;" : "=f"(r) : "f"(x)); return r;
}
__device__ __forceinline__ float ss(float a, float b, float inv) {
    // 1 - (1 - a*b)^inv ; FFMA negate modifier makes the -a free
    return 1.0f - ex2a(lg2a(fmaf(-a, b, 1.0f)) * inv);
}

// ---------------------------------------------------------------------------
// Warp owns 2 rows; val[slot] is 8 B -> one LDS.64 per operand covers both
// rows. Scalar math (no f32x2 pack/unpack MOV bloat). Fully unrolled sweep
// so the 24 table LDGs batch early. Streaming stores (write-once output).
// ---------------------------------------------------------------------------
__global__ __launch_bounds__(256)
void schweizer_kernel(const float* __restrict__ x,
                      const float* __restrict__ lam_p,
                      float* __restrict__ out)
{
    __shared__ __align__(8) float val[WPB][NVAL][RPW];

    const int lane = threadIdx.x & 31;
    const int wrp  = threadIdx.x >> 5;
    const int r0   = (blockIdx.x * WPB + wrp) * RPW;

    const float lam = __ldg(lam_p);
    const float inv = 1.0f / lam;

    float (*v)[RPW] = val[wrp];

    // ---- prologue: s_i for 2 rows + passthrough ----------------------------
    if (lane < RPW * NF) {
        const float xv = __ldg(x + (size_t)r0 * NF + lane);
        const int f = lane % NF, r = lane / NF;
        v[f][r] = 1.0f - ex2a(lg2a(1.0f - xv) * lam);
        __stcs(out + (size_t)(r0 + r) * NCOLS + f, xv);
    } else if (lane < RPW * NF + RPW) {
        v[78][lane - RPW * NF] = 1.0f;                   // sentinel
    }
    __syncwarp();

    // ---- 66 pairwise products (vectorized over 2 rows) ---------------------
    #pragma unroll
    for (int p = lane; p < NPAIR; p += 32) {
        const uint32_t w = __ldg(&d_pt.v[p]);
        const float2 a = *(const float2*)v[w & 0xFFu];
        const float2 b = *(const float2*)v[w >> 8];
        float2 r2;
        r2.x = a.x * b.x;
        r2.y = a.y * b.y;
        *(float2*)v[12 + p] = r2;
    }
    __syncwarp();

    // ---- main sweep: 24 full 32-column groups, fully unrolled ---------------
    const char* vb = (const char*)v;
    float* __restrict__ o0 = out + (size_t)r0 * NCOLS + NF;
    float* __restrict__ o1 = o0 + NCOLS;

    #pragma unroll
    for (int k = 0; k < 24; ++k) {
        const int c = k * 32 + lane;
        const uint32_t w = __ldg(&d_ct.v[c]);
        const float2 a = *(const float2*)(vb + (w & 0xFFFFu));
        const float2 b = *(const float2*)(vb + (w >> 16));
        __stcs(o0 + c, ss(a.x, b.x, inv));
        __stcs(o1 + c, ss(a.y, b.y, inv));
    }
    if (lane < NCOMB - 768) {                            // cols 768..780
        const int c = 768 + lane;
        const uint32_t w = __ldg(&d_ct.v[c]);
        const float2 a = *(const float2*)(vb + (w & 0xFFFFu));
        const float2 b = *(const float2*)(vb + (w >> 16));
        __stcs(o0 + c, ss(a.x, b.x, inv));
        __stcs(o1 + c, ss(a.y, b.y, inv));
    }
}

extern "C" void kernel_launch(void* const* d_in, const int* in_sizes, int n_in,
                              void* d_out, int out_size)
{
    const float* x   = (const float*)d_in[0];
    const float* lam = (const float*)d_in[1];
    float*       out = (float*)d_out;

    schweizer_kernel<<<NROWS / (WPB * RPW), 256>>>(x, lam, out);
}

// round 13
// speedup vs baseline: 1.1106x; 1.0312x over previous
#include <cuda_runtime.h>
#include <cstdint>

#define NF     12
#define NPAIR  66
#define NCOMB  781
#define NCOLS  793
#define NROWS  32768
#define WPB    4            // warps per block (finer scheduling granularity)
#define RPW    2            // rows per warp
#define NVAL   80           // slots: 0..11 s_i, 12..77 pairs, 78 = 1.0, pad

// pair id, lexicographic i<j
constexpr int pid(int i, int j) { return i * (2 * NF - i - 1) / 2 + (j - i - 1); }

// ---------------------------------------------------------------------------
// Combo table: two 16-bit BYTE offsets into val[NVAL][2] (8 B per slot).
// combo value p = val[a] * val[b]; q = 1 - p via FFMA with negate modifier.
// ---------------------------------------------------------------------------
struct CTbl { uint32_t v[NCOMB]; };
struct PTbl { uint32_t v[NPAIR]; };

constexpr CTbl make_ctbl() {
    CTbl t{};
    int p = 0;
    for (int i = 0; i < NF; ++i)                    // size 2: P2 * 1
        for (int j = i + 1; j < NF; ++j)
            t.v[p++] = (uint32_t)((12 + pid(i, j)) * 8)
                     | ((uint32_t)(78 * 8) << 16);
    for (int i = 0; i < NF; ++i)                    // size 3: P2(i,j) * s_k
        for (int j = i + 1; j < NF; ++j)
            for (int k = j + 1; k < NF; ++k)
                t.v[p++] = (uint32_t)((12 + pid(i, j)) * 8)
                         | ((uint32_t)(k * 8) << 16);
    for (int i = 0; i < NF; ++i)                    // size 4: P2(i,j) * P2(k,l)
        for (int j = i + 1; j < NF; ++j)
            for (int k = j + 1; k < NF; ++k)
                for (int l = k + 1; l < NF; ++l)
                    t.v[p++] = (uint32_t)((12 + pid(i, j)) * 8)
                             | ((uint32_t)((12 + pid(k, l)) * 8) << 16);
    return t;
}
constexpr PTbl make_ptbl() {
    PTbl t{};
    int p = 0;
    for (int i = 0; i < NF; ++i)
        for (int j = i + 1; j < NF; ++j)
            t.v[p++] = (uint32_t)i | ((uint32_t)j << 8);
    return t;
}

__device__ const CTbl d_ct = make_ctbl();
__device__ const PTbl d_pt = make_ptbl();

__device__ __forceinline__ float lg2a(float x) {
    float r; asm("lg2.approx.f32 %0,%1;" : "=f"(r) : "f"(x)); return r;
}
__device__ __forceinline__ float ex2a(float x) {
    float r; asm("ex2.approx.f32 %0,%1;" : "=f"(r) : "f"(x)); return r;
}
__device__ __forceinline__ float ss(float a, float b, float inv) {
    // 1 - (1 - a*b)^inv ; FFMA negate modifier makes the -a free
    return 1.0f - ex2a(lg2a(fmaf(-a, b, 1.0f)) * inv);
}

// ---------------------------------------------------------------------------
// Warp owns 2 rows; val[slot] is 8 B -> one LDS.64 per operand covers both
// rows. Scalar math, fully unrolled sweep, streaming stores. 128-thread
// blocks x 4096: fine-grained distribution, no block-slot limit (regs=32
// -> 16 blocks/SM possible), minimal wave raggedness and tail skew.
// ---------------------------------------------------------------------------
__global__ __launch_bounds__(128)
void schweizer_kernel(const float* __restrict__ x,
                      const float* __restrict__ lam_p,
                      float* __restrict__ out)
{
    __shared__ __align__(8) float val[WPB][NVAL][RPW];

    const int lane = threadIdx.x & 31;
    const int wrp  = threadIdx.x >> 5;
    const int r0   = (blockIdx.x * WPB + wrp) * RPW;

    const float lam = __ldg(lam_p);
    const float inv = 1.0f / lam;

    float (*v)[RPW] = val[wrp];

    // ---- prologue: s_i for 2 rows + passthrough ----------------------------
    if (lane < RPW * NF) {
        const float xv = __ldg(x + (size_t)r0 * NF + lane);
        const int f = lane % NF, r = lane / NF;
        v[f][r] = 1.0f - ex2a(lg2a(1.0f - xv) * lam);
        __stcs(out + (size_t)(r0 + r) * NCOLS + f, xv);
    } else if (lane < RPW * NF + RPW) {
        v[78][lane - RPW * NF] = 1.0f;                   // sentinel
    }
    __syncwarp();

    // ---- 66 pairwise products (vectorized over 2 rows) ---------------------
    #pragma unroll
    for (int p = lane; p < NPAIR; p += 32) {
        const uint32_t w = __ldg(&d_pt.v[p]);
        const float2 a = *(const float2*)v[w & 0xFFu];
        const float2 b = *(const float2*)v[w >> 8];
        float2 r2;
        r2.x = a.x * b.x;
        r2.y = a.y * b.y;
        *(float2*)v[12 + p] = r2;
    }
    __syncwarp();

    // ---- main sweep: 24 full 32-column groups, fully unrolled ---------------
    const char* vb = (const char*)v;
    float* __restrict__ o0 = out + (size_t)r0 * NCOLS + NF;
    float* __restrict__ o1 = o0 + NCOLS;

    #pragma unroll
    for (int k = 0; k < 24; ++k) {
        const int c = k * 32 + lane;
        const uint32_t w = __ldg(&d_ct.v[c]);
        const float2 a = *(const float2*)(vb + (w & 0xFFFFu));
        const float2 b = *(const float2*)(vb + (w >> 16));
        __stcs(o0 + c, ss(a.x, b.x, inv));
        __stcs(o1 + c, ss(a.y, b.y, inv));
    }
    if (lane < NCOMB - 768) {                            // cols 768..780
        const int c = 768 + lane;
        const uint32_t w = __ldg(&d_ct.v[c]);
        const float2 a = *(const float2*)(vb + (w & 0xFFFFu));
        const float2 b = *(const float2*)(vb + (w >> 16));
        __stcs(o0 + c, ss(a.x, b.x, inv));
        __stcs(o1 + c, ss(a.y, b.y, inv));
    }
}

extern "C" void kernel_launch(void* const* d_in, const int* in_sizes, int n_in,
                              void* d_out, int out_size)
{
    const float* x   = (const float*)d_in[0];
    const float* lam = (const float*)d_in[1];
    float*       out = (float*)d_out;

    schweizer_kernel<<<NROWS / (WPB * RPW), WPB * 32>>>(x, lam, out);
}